// round 15
// baseline (speedup 1.0000x reference)
#include <cuda_runtime.h>
#include <cstdint>

#define WINDOW 40
#define EE 8
#define NSTOCK 8000
#define TDIM 64
#define FDIM 64
#define INCH 144
#define LOUT 36

__device__ float g_xcol[WINDOW * EE * NSTOCK];      // [col][n]  staged slice
__device__ float g_rank[WINDOW * EE * NSTOCK];      // [col][n]
__device__ float g_rank_t[NSTOCK * WINDOW * EE];    // [n][col]

// ---------------------------------------------------------------------------
// Gather: x[:, 24:64, 0:8] -> g_xcol[col][n], full sector efficiency.
// ---------------------------------------------------------------------------
__global__ void __launch_bounds__(256) gather_kernel(const float* __restrict__ x) {
    __shared__ float tile[8][128];
    const int twv = blockIdx.x;
    const int n0 = blockIdx.y * 128;
    const int t = threadIdx.x;

    {
        int nl = t >> 1, half = t & 1;
        int n = n0 + nl;
        if (n < NSTOCK) {
            float4 v = *(const float4*)(x + (size_t)n * (TDIM * FDIM) + (24 + twv) * FDIM + half * 4);
            tile[half * 4 + 0][nl] = v.x;
            tile[half * 4 + 1][nl] = v.y;
            tile[half * 4 + 2][nl] = v.z;
            tile[half * 4 + 3][nl] = v.w;
        }
    }
    __syncthreads();
    {
        int idx = t * 4;
        int c = idx >> 7, nl = idx & 127;
        if (n0 + nl + 3 < NSTOCK) {
            float4 v = *(const float4*)(&tile[c][nl]);
            *(float4*)(g_xcol + (size_t)(twv * 8 + c) * NSTOCK + n0 + nl) = v;
        } else {
            for (int j = 0; j < 4; j++)
                if (n0 + nl + j < NSTOCK)
                    g_xcol[(size_t)(twv * 8 + c) * NSTOCK + n0 + nl + j] = tile[c][nl + j];
        }
    }
}

// ---------------------------------------------------------------------------
// Kernel A: exact descending rank, 3 CTAs/SM (single wave for 320 blocks).
// 4096 uniform value bins; u32 hist (atomic old = within-bin index, kept as
// packed u16 in regs); values reloaded (L1-hot) in P3/P4; tie-break via
// separate key[] u32 + n16[] u16 arrays; exact semantics incl. ties.
// smem: hist 4100 w (16400 B) | key 8000 u32 (32000 B) | n16 8000 u16 (16000 B)
//       = 64400 B -> 3 CTAs/SM needs <= 75.6 KB ok.
// ---------------------------------------------------------------------------
#define RT 512
#define NB4 4096
#define SMEM_R ((NB4 + 4) * 4 + NSTOCK * 4 + NSTOCK * 2)

__device__ __forceinline__ unsigned int okey(float f) {
    unsigned int u = __float_as_uint(f);
    return (u & 0x80000000u) ? ~u : (u | 0x80000000u);
}

__global__ void __launch_bounds__(RT, 3) rank_kernel() {
    extern __shared__ unsigned char smem_raw[];
    unsigned int* hist = (unsigned int*)smem_raw;                                  // 4100 w
    unsigned int* key  = (unsigned int*)(smem_raw + (NB4 + 4) * 4);                // 8000 u32
    unsigned short* n16 = (unsigned short*)(smem_raw + (NB4 + 4) * 4 + NSTOCK * 4);// 8000 u16

    __shared__ unsigned int wsum[16];

    const int col = blockIdx.x;
    const int tid = threadIdx.x;
    const unsigned int lane = tid & 31u;
    const unsigned int wid  = tid >> 5;

    // zero histogram (4096 words via uint4)
    {
        uint4 z4 = make_uint4(0u, 0u, 0u, 0u);
        uint4* hv = (uint4*)hist;
#pragma unroll
        for (int i = 0; i < 2; i++) hv[tid + (i << 9)] = z4;
        if (tid == 0) { hist[4096] = 0u; hist[4097] = 0u; hist[4098] = 0u; hist[4099] = 0u; }
    }
    __syncthreads();

    const float* colp = g_xcol + (size_t)col * NSTOCK;

    // P1: load value, bin (4096 uniform over [-4,4]), histogram atomic;
    // keep ONLY the within-bin index (u16, packed pairs -> 8 regs).
    unsigned int idxp[8];
#pragma unroll
    for (int i = 0; i < 16; i++) {
        int n = tid + (i << 9);
        unsigned int idx = 0u;
        if (n < NSTOCK) {
            float v = __ldg(colp + n);
            int b = __float2int_rd(fmaf(v, 512.0f, 2048.0f));
            b = (b < 0) ? 0 : (b > NB4 - 1 ? NB4 - 1 : b);
            idx = atomicAdd(&hist[b], 1u);
        }
        if (i & 1) idxp[i >> 1] |= (idx << 16);
        else       idxp[i >> 1]  = idx;
    }
    __syncthreads();

    // exclusive prefix over 4096 u32 bins (8/thread via uint4)
    {
        uint4* hv = (uint4*)hist;
        uint4 a[2];
        unsigned int s = 0;
#pragma unroll
        for (int j = 0; j < 2; j++) {
            a[j] = hv[tid * 2 + j];
            s += a[j].x + a[j].y + a[j].z + a[j].w;
        }
        unsigned int v = s;
#pragma unroll
        for (int o = 1; o < 32; o <<= 1) {
            unsigned int t = __shfl_up_sync(0xFFFFFFFFu, v, o);
            if (lane >= (unsigned)o) v += t;
        }
        if (lane == 31u) wsum[wid] = v;
        __syncthreads();
        if (wid == 0) {
            unsigned int orig = (lane < 16u) ? wsum[lane] : 0u;
            unsigned int w = orig;
#pragma unroll
            for (int o = 1; o < 32; o <<= 1) {
                unsigned int t = __shfl_up_sync(0xFFFFFFFFu, w, o);
                if (lane >= (unsigned)o) w += t;
            }
            if (lane < 16u) wsum[lane] = w - orig;
        }
        __syncthreads();
        unsigned int run = wsum[wid] + (v - s);
#pragma unroll
        for (int j = 0; j < 2; j++) {
            unsigned int* p = &a[j].x;
#pragma unroll
            for (int k = 0; k < 4; k++) {
                unsigned int c = p[k];
                p[k] = run;
                run += c;
            }
            hv[tid * 2 + j] = a[j];
        }
        if (tid == 0) hist[4096] = (unsigned int)NSTOCK;   // sentinel
    }
    __syncthreads();

    // P3: reload value (L1-hot), scatter key + index (no atomics)
#pragma unroll
    for (int i = 0; i < 16; i++) {
        int n = tid + (i << 9);
        if (n < NSTOCK) {
            float v = __ldg(colp + n);
            int b = __float2int_rd(fmaf(v, 512.0f, 2048.0f));
            b = (b < 0) ? 0 : (b > NB4 - 1 ? NB4 - 1 : b);
            unsigned int idx = (idxp[i >> 1] >> ((i & 1) * 16)) & 0xFFFFu;
            unsigned int pos = hist[b] + idx;
            key[pos] = okey(v);
            n16[pos] = (unsigned short)n;
        }
    }
    __syncthreads();

    // P4: rank = above-segment + in-segment {greater, or equal with smaller n}
    float* dst = g_rank + (size_t)col * NSTOCK;
#pragma unroll
    for (int i = 0; i < 16; i++) {
        int n = tid + (i << 9);
        if (n < NSTOCK) {
            float v = __ldg(colp + n);
            int b = __float2int_rd(fmaf(v, 512.0f, 2048.0f));
            b = (b < 0) ? 0 : (b > NB4 - 1 ? NB4 - 1 : b);
            unsigned int start = hist[b];
            unsigned int end = hist[b + 1];
            unsigned int g = (unsigned int)NSTOCK - end;
            if (end - start > 1u) {
                unsigned int K = okey(v);
                for (unsigned int q = start; q < end; q++) {
                    unsigned int kq = key[q];
                    if (kq > K) g++;
                    else if (kq == K && (int)n16[q] < n) g++;   // stable tie-break
                }
            }
            dst[n] = (float)g * (1.0f / (float)NSTOCK);
        }
    }
}

// ---------------------------------------------------------------------------
// Transpose [col][n] -> [n][col]
// ---------------------------------------------------------------------------
__global__ void transpose_kernel() {
    __shared__ float tile[32][33];
    const int c0 = blockIdx.x * 32;
    const int n0 = blockIdx.y * 32;
    const int tx = threadIdx.x, ty = threadIdx.y;
    tile[ty][tx] = g_rank[(size_t)(c0 + ty) * NSTOCK + n0 + tx];
    __syncthreads();
    g_rank_t[(size_t)(n0 + ty) * (WINDOW * EE) + c0 + tx] = tile[tx][ty];
}

// ---------------------------------------------------------------------------
// Kernel B (R13-measured-best variant): fused stats (15+5 chains) + conv
// (out-channel 127) + linear; 1-level shfl reduction.
// ---------------------------------------------------------------------------
#define SID_STRIDE 328

__global__ void __launch_bounds__(320) main_kernel(
    const float* __restrict__ x,
    const float* __restrict__ conv_w,
    const float* __restrict__ conv_b,
    const float* __restrict__ lin_w,
    const float* __restrict__ lin_b,
    float* __restrict__ out)
{
    __shared__ __align__(16) float xe[59][8];
    __shared__ __align__(16) float stats[8 * SID_STRIDE];
    __shared__ __align__(16) float rank_row[WINDOW * EE];
    __shared__ float red[160][18];
    __shared__ float fin[LOUT];

    const int n = blockIdx.x;
    const int tid = threadIdx.x;
    const float* xn = x + (size_t)n * (TDIM * FDIM);

    if (tid < 118) {
        int row = tid >> 1, half = tid & 1;
        float4 v = *(const float4*)(xn + (5 + row) * FDIM + half * 4);
        *(float4*)(&xe[row][half * 4]) = v;
    }
    if (tid >= 128 && tid < 128 + (WINDOW * EE) / 4) {
        const float4* rsrc = (const float4*)(g_rank_t + (size_t)n * (WINDOW * EE));
        ((float4*)rank_row)[tid - 128] = rsrc[tid - 128];
    }
    __syncthreads();

    // stats: one (tw, ee) task per thread; 15+5 sub-chain merge
    {
        int tw = tid >> 3, ee = tid & 7;

        float s15 = 0.f, q15 = 0.f, mx15 = -1e30f, mn15 = 1e30f;
#pragma unroll
        for (int j = 0; j < 15; j++) {
            float v = xe[tw + j][ee];
            s15 += v; q15 = fmaf(v, v, q15);
            mx15 = fmaxf(mx15, v); mn15 = fminf(mn15, v);
        }
        float s5 = 0.f, q5 = 0.f, mx5 = -1e30f, mn5 = 1e30f;
#pragma unroll
        for (int j = 15; j < 20; j++) {
            float v = xe[tw + j][ee];
            s5 += v; q5 = fmaf(v, v, q5);
            mx5 = fmaxf(mx5, v); mn5 = fminf(mn5, v);
        }
        float s20 = s15 + s5, q20 = q15 + q5;
        float mx20 = fmaxf(mx15, mx5), mn20 = fminf(mn15, mn5);
        float m20 = s20 * 0.05f;
        float m5  = s5 * 0.2f;
        float sd20 = sqrtf(fmaxf(fmaf(-s20, m20, q20), 0.f) * (1.0f / 19.0f));
        float sd5  = sqrtf(fmaxf(fmaf(-s5, m5, q5), 0.f) * 0.25f);

        float* st = stats + tw * 8 + ee;
        st[0 * SID_STRIDE] = m5;   st[1 * SID_STRIDE] = sd5;
        st[2 * SID_STRIDE] = mx5;  st[3 * SID_STRIDE] = mn5;
        st[4 * SID_STRIDE] = m20;  st[5 * SID_STRIDE] = sd20;
        st[6 * SID_STRIDE] = mx20; st[7 * SID_STRIDE] = mn20;
    }
    __syncthreads();

    // conv: two threads per channel, each covering 18 of 36 outputs
    float acc[18];
#pragma unroll
    for (int j = 0; j < 18; j++) acc[j] = 0.f;

    const int hh = (tid >= 160) ? 1 : 0;
    const int c  = tid - hh * 160;
    const int l0 = hh * 18;

    if (c < INCH) {
        const float* wp = conv_w + 127 * (INCH * 5) + c * 5;
        float w0 = __ldg(wp + 0), w1 = __ldg(wp + 1), w2 = __ldg(wp + 2),
              w3 = __ldg(wp + 3), w4 = __ldg(wp + 4);

        if (c < FDIM) {
            const float* src = xn + (24 + l0) * FDIM + c;
#pragma unroll
            for (int tt = 0; tt < 22; tt++) {
                float v = __ldg(src + tt * FDIM);
#pragma unroll
                for (int k = 0; k < 5; k++) {
                    int j = tt - k;
                    if (j >= 0 && j < 18) {
                        float wk = (k == 0) ? w0 : (k == 1) ? w1 : (k == 2) ? w2 : (k == 3) ? w3 : w4;
                        acc[j] += v * wk;
                    }
                }
            }
        } else {
            int cc = c - FDIM;
            int grp = (cc >= 40) ? 1 : 0;
            int r = cc - grp * 40;
            int se = r >> 3;
            int ee = r & 7;
            const float* s_src;
            if (se == 2) {
                s_src = rank_row + ee;
            } else {
                int statid = (se < 2 ? se : se - 1) + grp * 4;
                s_src = stats + statid * SID_STRIDE + ee;
            }
            s_src += l0 * 8;
#pragma unroll
            for (int tt = 0; tt < 22; tt++) {
                float v = s_src[tt * 8];
#pragma unroll
                for (int k = 0; k < 5; k++) {
                    int j = tt - k;
                    if (j >= 0 && j < 18) {
                        float wk = (k == 0) ? w0 : (k == 1) ? w1 : (k == 2) ? w2 : (k == 3) ? w3 : w4;
                        acc[j] += v * wk;
                    }
                }
            }
        }
    }

    // 1-level butterfly (xor16) -> 16 partials/warp -> smem -> 36-thread finish
#pragma unroll
    for (int j = 0; j < 18; j++)
        acc[j] += __shfl_xor_sync(0xFFFFFFFFu, acc[j], 16);
    {
        const int w = tid >> 5;
        if ((tid & 31) < 16) {
#pragma unroll
            for (int j = 0; j < 18; j++) red[w * 16 + (tid & 15)][j] = acc[j];
        }
    }
    __syncthreads();

    if (tid < LOUT) {
        int h2 = (tid >= 18) ? 1 : 0;
        int j = tid - h2 * 18;
        const float* rp = &red[h2 * 80][j];
        float s = __ldg(conv_b + 127);
#pragma unroll
        for (int i = 0; i < 80; i++) s += rp[i * 18];
        float hv = (s >= 0.f) ? s : 0.01f * s;
        fin[tid] = hv * __ldg(lin_w + tid);
    }
    __syncthreads();

    if (tid == 0) {
        float s = __ldg(lin_b);
        for (int l = 0; l < LOUT; l++) s += fin[l];
        out[n] = s;
    }
}

// ---------------------------------------------------------------------------
extern "C" void kernel_launch(void* const* d_in, const int* in_sizes, int n_in,
                              void* d_out, int out_size) {
    const float* x      = (const float*)d_in[0];
    const float* conv_w = (const float*)d_in[1];
    const float* conv_b = (const float*)d_in[2];
    const float* lin_w  = (const float*)d_in[3];
    const float* lin_b  = (const float*)d_in[4];
    float* out = (float*)d_out;

    cudaFuncSetAttribute(rank_kernel, cudaFuncAttributeMaxDynamicSharedMemorySize, SMEM_R);

    gather_kernel<<<dim3(WINDOW, (NSTOCK + 127) / 128), 256>>>(x);
    rank_kernel<<<WINDOW * EE, RT, SMEM_R>>>();
    transpose_kernel<<<dim3((WINDOW * EE) / 32, NSTOCK / 32), dim3(32, 32)>>>();
    main_kernel<<<NSTOCK, 320>>>(x, conv_w, conv_b, lin_w, lin_b, out);
}

// round 16
// speedup vs baseline: 1.0681x; 1.0681x over previous
#include <cuda_runtime.h>
#include <cstdint>

#define WINDOW 40
#define EE 8
#define NSTOCK 8000
#define TDIM 64
#define FDIM 64
#define INCH 144
#define LOUT 36

__device__ float g_xcol[WINDOW * EE * NSTOCK];      // [col][n]  staged slice
__device__ float g_rank[WINDOW * EE * NSTOCK];      // [col][n]
__device__ float g_rank_t[NSTOCK * WINDOW * EE];    // [n][col]

// ---------------------------------------------------------------------------
// Gather: x[:, 24:64, 0:8] -> g_xcol[col][n], full sector efficiency.
// ---------------------------------------------------------------------------
__global__ void __launch_bounds__(256) gather_kernel(const float* __restrict__ x) {
    __shared__ float tile[8][128];
    const int twv = blockIdx.x;
    const int n0 = blockIdx.y * 128;
    const int t = threadIdx.x;

    {
        int nl = t >> 1, half = t & 1;
        int n = n0 + nl;
        if (n < NSTOCK) {
            float4 v = *(const float4*)(x + (size_t)n * (TDIM * FDIM) + (24 + twv) * FDIM + half * 4);
            tile[half * 4 + 0][nl] = v.x;
            tile[half * 4 + 1][nl] = v.y;
            tile[half * 4 + 2][nl] = v.z;
            tile[half * 4 + 3][nl] = v.w;
        }
    }
    __syncthreads();
    {
        int idx = t * 4;
        int c = idx >> 7, nl = idx & 127;
        if (n0 + nl + 3 < NSTOCK) {
            float4 v = *(const float4*)(&tile[c][nl]);
            *(float4*)(g_xcol + (size_t)(twv * 8 + c) * NSTOCK + n0 + nl) = v;
        } else {
            for (int j = 0; j < 4; j++)
                if (n0 + nl + j < NSTOCK)
                    g_xcol[(size_t)(twv * 8 + c) * NSTOCK + n0 + nl + j] = tile[c][nl + j];
        }
    }
}

// ---------------------------------------------------------------------------
// Kernel A: exact descending rank. RT=1024, 2 CTAs/SM -> 100% occupancy,
// 1.08 waves. 8192 uniform value bins, u32 hist (atomic old = within-bin
// index, kept as packed u16 -> 4 regs), values reloaded in P3/P4 (L2-hot),
// split tie-break arrays: key[] u32 + n16[] u16. Exact incl. stable ties.
// smem: hist 8196 w (32784 B) + key 32000 B + n16 16000 B = 80784 B.
// ---------------------------------------------------------------------------
#define RT 1024
#define NB 8192
#define SMEM_R ((NB + 4) * 4 + NSTOCK * 4 + NSTOCK * 2)

__device__ __forceinline__ unsigned int okey(float f) {
    unsigned int u = __float_as_uint(f);
    return (u & 0x80000000u) ? ~u : (u | 0x80000000u);
}

__device__ __forceinline__ int binof(float v) {
    int b = __float2int_rd(fmaf(v, 1024.0f, 4096.0f));
    return (b < 0) ? 0 : (b > NB - 1 ? NB - 1 : b);
}

__global__ void __launch_bounds__(RT, 2) rank_kernel() {
    extern __shared__ unsigned char smem_raw[];
    unsigned int* hist = (unsigned int*)smem_raw;                                   // 8196 w
    unsigned int* key  = (unsigned int*)(smem_raw + (NB + 4) * 4);                  // 8000 u32
    unsigned short* n16 = (unsigned short*)(smem_raw + (NB + 4) * 4 + NSTOCK * 4);  // 8000 u16

    __shared__ unsigned int wsum[32];

    const int col = blockIdx.x;
    const int tid = threadIdx.x;
    const unsigned int lane = tid & 31u;
    const unsigned int wid  = tid >> 5;

    // zero histogram (8192 words via uint4)
    {
        uint4 z4 = make_uint4(0u, 0u, 0u, 0u);
        uint4* hv = (uint4*)hist;
#pragma unroll
        for (int i = 0; i < 2; i++) hv[tid + (i << 10)] = z4;
        if (tid == 0) { hist[NB] = 0u; hist[NB + 1] = 0u; hist[NB + 2] = 0u; hist[NB + 3] = 0u; }
    }
    __syncthreads();

    const float* colp = g_xcol + (size_t)col * NSTOCK;

    // P1: load value, bin, histogram atomic; keep ONLY within-bin index (u16 pairs)
    unsigned int idxp[4];
#pragma unroll
    for (int i = 0; i < 8; i++) {
        int n = tid + (i << 10);
        unsigned int idx = 0u;
        if (n < NSTOCK)
            idx = atomicAdd(&hist[binof(__ldg(colp + n))], 1u);
        if (i & 1) idxp[i >> 1] |= (idx << 16);
        else       idxp[i >> 1]  = idx;
    }
    __syncthreads();

    // exclusive prefix over 8192 u32 bins (8 bins/thread via 2x uint4)
    {
        uint4* hv = (uint4*)hist;
        uint4 a[2];
        unsigned int s = 0;
#pragma unroll
        for (int j = 0; j < 2; j++) {
            a[j] = hv[tid * 2 + j];
            s += a[j].x + a[j].y + a[j].z + a[j].w;
        }
        unsigned int v = s;
#pragma unroll
        for (int o = 1; o < 32; o <<= 1) {
            unsigned int t = __shfl_up_sync(0xFFFFFFFFu, v, o);
            if (lane >= (unsigned)o) v += t;
        }
        if (lane == 31u) wsum[wid] = v;
        __syncthreads();
        if (wid == 0) {
            unsigned int orig = wsum[lane];
            unsigned int w = orig;
#pragma unroll
            for (int o = 1; o < 32; o <<= 1) {
                unsigned int t = __shfl_up_sync(0xFFFFFFFFu, w, o);
                if (lane >= (unsigned)o) w += t;
            }
            wsum[lane] = w - orig;
        }
        __syncthreads();
        unsigned int run = wsum[wid] + (v - s);
#pragma unroll
        for (int j = 0; j < 2; j++) {
            unsigned int* p = &a[j].x;
#pragma unroll
            for (int k = 0; k < 4; k++) {
                unsigned int c = p[k];
                p[k] = run;
                run += c;
            }
            hv[tid * 2 + j] = a[j];
        }
        if (tid == 0) hist[NB] = (unsigned int)NSTOCK;   // sentinel
    }
    __syncthreads();

    // P3: reload value (L2-hot), scatter key + n (no atomics)
#pragma unroll
    for (int i = 0; i < 8; i++) {
        int n = tid + (i << 10);
        if (n < NSTOCK) {
            float v = __ldg(colp + n);
            unsigned int idx = (idxp[i >> 1] >> ((i & 1) * 16)) & 0xFFFFu;
            unsigned int pos = hist[binof(v)] + idx;
            key[pos] = okey(v);
            n16[pos] = (unsigned short)n;
        }
    }
    __syncthreads();

    // P4: rank = above-segment + in-segment {greater, or tie with smaller n}
    float* dst = g_rank + (size_t)col * NSTOCK;
#pragma unroll
    for (int i = 0; i < 8; i++) {
        int n = tid + (i << 10);
        if (n < NSTOCK) {
            float v = __ldg(colp + n);
            int b = binof(v);
            unsigned int start = hist[b];
            unsigned int end = hist[b + 1];
            unsigned int g = (unsigned int)NSTOCK - end;
            if (end - start > 1u) {
                unsigned int K = okey(v);
                for (unsigned int q = start; q < end; q++) {
                    unsigned int kq = key[q];
                    if (kq > K) g++;
                    else if (kq == K && (int)n16[q] < n) g++;   // stable tie-break
                }
            }
            dst[n] = (float)g * (1.0f / (float)NSTOCK);
        }
    }
}

// ---------------------------------------------------------------------------
// Transpose [col][n] -> [n][col]
// ---------------------------------------------------------------------------
__global__ void transpose_kernel() {
    __shared__ float tile[32][33];
    const int c0 = blockIdx.x * 32;
    const int n0 = blockIdx.y * 32;
    const int tx = threadIdx.x, ty = threadIdx.y;
    tile[ty][tx] = g_rank[(size_t)(c0 + ty) * NSTOCK + n0 + tx];
    __syncthreads();
    g_rank_t[(size_t)(n0 + ty) * (WINDOW * EE) + c0 + tx] = tile[tx][ty];
}

// ---------------------------------------------------------------------------
// Kernel B: fused stats (15+5 chains) + conv (out-channel 127) + linear;
// 1-level shfl reduction. (Measured-best main variant.)
// ---------------------------------------------------------------------------
#define SID_STRIDE 328

__global__ void __launch_bounds__(320) main_kernel(
    const float* __restrict__ x,
    const float* __restrict__ conv_w,
    const float* __restrict__ conv_b,
    const float* __restrict__ lin_w,
    const float* __restrict__ lin_b,
    float* __restrict__ out)
{
    __shared__ __align__(16) float xe[59][8];
    __shared__ __align__(16) float stats[8 * SID_STRIDE];
    __shared__ __align__(16) float rank_row[WINDOW * EE];
    __shared__ float red[160][18];
    __shared__ float fin[LOUT];

    const int n = blockIdx.x;
    const int tid = threadIdx.x;
    const float* xn = x + (size_t)n * (TDIM * FDIM);

    if (tid < 118) {
        int row = tid >> 1, half = tid & 1;
        float4 v = *(const float4*)(xn + (5 + row) * FDIM + half * 4);
        *(float4*)(&xe[row][half * 4]) = v;
    }
    if (tid >= 128 && tid < 128 + (WINDOW * EE) / 4) {
        const float4* rsrc = (const float4*)(g_rank_t + (size_t)n * (WINDOW * EE));
        ((float4*)rank_row)[tid - 128] = rsrc[tid - 128];
    }
    __syncthreads();

    // stats: one (tw, ee) task per thread; 15+5 sub-chain merge
    {
        int tw = tid >> 3, ee = tid & 7;

        float s15 = 0.f, q15 = 0.f, mx15 = -1e30f, mn15 = 1e30f;
#pragma unroll
        for (int j = 0; j < 15; j++) {
            float v = xe[tw + j][ee];
            s15 += v; q15 = fmaf(v, v, q15);
            mx15 = fmaxf(mx15, v); mn15 = fminf(mn15, v);
        }
        float s5 = 0.f, q5 = 0.f, mx5 = -1e30f, mn5 = 1e30f;
#pragma unroll
        for (int j = 15; j < 20; j++) {
            float v = xe[tw + j][ee];
            s5 += v; q5 = fmaf(v, v, q5);
            mx5 = fmaxf(mx5, v); mn5 = fminf(mn5, v);
        }
        float s20 = s15 + s5, q20 = q15 + q5;
        float mx20 = fmaxf(mx15, mx5), mn20 = fminf(mn15, mn5);
        float m20 = s20 * 0.05f;
        float m5  = s5 * 0.2f;
        float sd20 = sqrtf(fmaxf(fmaf(-s20, m20, q20), 0.f) * (1.0f / 19.0f));
        float sd5  = sqrtf(fmaxf(fmaf(-s5, m5, q5), 0.f) * 0.25f);

        float* st = stats + tw * 8 + ee;
        st[0 * SID_STRIDE] = m5;   st[1 * SID_STRIDE] = sd5;
        st[2 * SID_STRIDE] = mx5;  st[3 * SID_STRIDE] = mn5;
        st[4 * SID_STRIDE] = m20;  st[5 * SID_STRIDE] = sd20;
        st[6 * SID_STRIDE] = mx20; st[7 * SID_STRIDE] = mn20;
    }
    __syncthreads();

    // conv: two threads per channel, each covering 18 of 36 outputs
    float acc[18];
#pragma unroll
    for (int j = 0; j < 18; j++) acc[j] = 0.f;

    const int hh = (tid >= 160) ? 1 : 0;
    const int c  = tid - hh * 160;
    const int l0 = hh * 18;

    if (c < INCH) {
        const float* wp = conv_w + 127 * (INCH * 5) + c * 5;
        float w0 = __ldg(wp + 0), w1 = __ldg(wp + 1), w2 = __ldg(wp + 2),
              w3 = __ldg(wp + 3), w4 = __ldg(wp + 4);

        if (c < FDIM) {
            const float* src = xn + (24 + l0) * FDIM + c;
#pragma unroll
            for (int tt = 0; tt < 22; tt++) {
                float v = __ldg(src + tt * FDIM);
#pragma unroll
                for (int k = 0; k < 5; k++) {
                    int j = tt - k;
                    if (j >= 0 && j < 18) {
                        float wk = (k == 0) ? w0 : (k == 1) ? w1 : (k == 2) ? w2 : (k == 3) ? w3 : w4;
                        acc[j] += v * wk;
                    }
                }
            }
        } else {
            int cc = c - FDIM;
            int grp = (cc >= 40) ? 1 : 0;
            int r = cc - grp * 40;
            int se = r >> 3;
            int ee = r & 7;
            const float* s_src;
            if (se == 2) {
                s_src = rank_row + ee;
            } else {
                int statid = (se < 2 ? se : se - 1) + grp * 4;
                s_src = stats + statid * SID_STRIDE + ee;
            }
            s_src += l0 * 8;
#pragma unroll
            for (int tt = 0; tt < 22; tt++) {
                float v = s_src[tt * 8];
#pragma unroll
                for (int k = 0; k < 5; k++) {
                    int j = tt - k;
                    if (j >= 0 && j < 18) {
                        float wk = (k == 0) ? w0 : (k == 1) ? w1 : (k == 2) ? w2 : (k == 3) ? w3 : w4;
                        acc[j] += v * wk;
                    }
                }
            }
        }
    }

    // 1-level butterfly (xor16) -> 16 partials/warp -> smem -> 36-thread finish
#pragma unroll
    for (int j = 0; j < 18; j++)
        acc[j] += __shfl_xor_sync(0xFFFFFFFFu, acc[j], 16);
    {
        const int w = tid >> 5;
        if ((tid & 31) < 16) {
#pragma unroll
            for (int j = 0; j < 18; j++) red[w * 16 + (tid & 15)][j] = acc[j];
        }
    }
    __syncthreads();

    if (tid < LOUT) {
        int h2 = (tid >= 18) ? 1 : 0;
        int j = tid - h2 * 18;
        const float* rp = &red[h2 * 80][j];
        float s = __ldg(conv_b + 127);
#pragma unroll
        for (int i = 0; i < 80; i++) s += rp[i * 18];
        float hv = (s >= 0.f) ? s : 0.01f * s;
        fin[tid] = hv * __ldg(lin_w + tid);
    }
    __syncthreads();

    if (tid == 0) {
        float s = __ldg(lin_b);
        for (int l = 0; l < LOUT; l++) s += fin[l];
        out[n] = s;
    }
}

// ---------------------------------------------------------------------------
extern "C" void kernel_launch(void* const* d_in, const int* in_sizes, int n_in,
                              void* d_out, int out_size) {
    const float* x      = (const float*)d_in[0];
    const float* conv_w = (const float*)d_in[1];
    const float* conv_b = (const float*)d_in[2];
    const float* lin_w  = (const float*)d_in[3];
    const float* lin_b  = (const float*)d_in[4];
    float* out = (float*)d_out;

    cudaFuncSetAttribute(rank_kernel, cudaFuncAttributeMaxDynamicSharedMemorySize, SMEM_R);

    gather_kernel<<<dim3(WINDOW, (NSTOCK + 127) / 128), 256>>>(x);
    rank_kernel<<<WINDOW * EE, RT, SMEM_R>>>();
    transpose_kernel<<<dim3((WINDOW * EE) / 32, NSTOCK / 32), dim3(32, 32)>>>();
    main_kernel<<<NSTOCK, 320>>>(x, conv_w, conv_b, lin_w, lin_b, out);
}